// round 7
// baseline (speedup 1.0000x reference)
#include <cuda_runtime.h>
#include <cstdint>

// Problem constants (N=32768, D=64, K=64 per reference)
#define NPTS 32768
#define DIM 64
#define NK 64
#define ROWS_PER_BLOCK 32
#define NTHREADS 32
#define NBLOCKS (NPTS / ROWS_PER_BLOCK)   // 1024

// Scratch (allocation-free rule: __device__ globals)
__device__ __align__(16) float d_negmuP[NK * DIM];  // -(means_k @ P_k), [K,D]
__device__ float d_C[NK];                           // per-cluster additive constant

// ---------------------------------------------------------------------------
// NaN-proof helpers (identity on valid inputs).
// ---------------------------------------------------------------------------
static __device__ __forceinline__ double safe_log(double v) {
    v = fabs(v);
    if (v < 1e-300) v = 1e-300;
    return log(v);
}

// digamma in double: bounded recurrence to x>=6, then asymptotic series.
// abs error < 1e-9 for x >= 0.5 — far below any wlp gap deciding the argmax.
static __device__ __forceinline__ double digamma_d(double x) {
    if (!(x > 1e-6)) x = 1e-6;
    double r = 0.0;
    #pragma unroll 1
    for (int it = 0; it < 8 && x < 6.0; ++it) { r -= 1.0 / x; x += 1.0; }
    double inv  = 1.0 / x;
    double inv2 = inv * inv;
    double s = inv2 * (1.0 / 12.0
             - inv2 * (1.0 / 120.0
             - inv2 * (1.0 / 252.0
             - inv2 * (1.0 / 240.0))));
    return r + log(x) - 0.5 * inv - s;
}

// ---------------------------------------------------------------------------
// Prep kernel: 1 block, 64 threads (thread k handles cluster k).
// v64a/v64b disambiguated by majority vote: dof in [65,114], mp in (0.5,10].
// C_k = log|P_k| - 0.5*D*log(2pi) - 0.5*D*log(dof_k)
//     + 0.5*(log_lambda_k - D/mp_k) + log_w_k;  negmuP[k,:] = -(means_k @ P_k)
// ---------------------------------------------------------------------------
__global__ void bgm_prep_kernel(const float* __restrict__ means,
                                const float* __restrict__ P,
                                const float* __restrict__ wc,
                                const float* __restrict__ v64a,
                                const float* __restrict__ v64b) {
    const int k = threadIdx.x;
    __shared__ float sdb[NK];   // digamma(b_j) - digamma(a_j+b_j)
    __shared__ int   votes;

    if (k == 0) votes = 0;
    __syncthreads();
    if (v64a[k] > 32.0f) atomicAdd(&votes, 1);
    __syncthreads();
    const bool a_is_dof = (votes >= 32);
    const float* __restrict__ dof = a_is_dof ? v64a : v64b;
    const float* __restrict__ mp  = a_is_dof ? v64b : v64a;

    const double dofk = (double)dof[k];
    double mpk = (double)mp[k];
    if (!(mpk > 1e-6)) mpk = 1e-6;

    double logdet = 0.0;
    for (int d = 0; d < DIM; ++d)
        logdet += safe_log((double)P[k * DIM * DIM + d * DIM + d]);

    double ll = (double)DIM * 0.69314718055994530942;  // D*log(2)
    for (int i = 0; i < DIM; ++i)
        ll += digamma_d(0.5 * (dofk - (double)i));

    const double a  = (double)wc[k];
    const double b  = (double)wc[NK + k];
    const double ds = digamma_d(a + b);
    sdb[k] = (float)(digamma_d(b) - ds);

    double C = logdet
             - 0.5 * (double)DIM * 1.8378770664093454836  // log(2*pi)
             - 0.5 * (double)DIM * safe_log(dofk)
             + 0.5 * (ll - (double)DIM / mpk)
             + digamma_d(a) - ds;

    __syncthreads();
    float pre = 0.0f;
    for (int j = 0; j < k; ++j) pre += sdb[j];   // exclusive cumsum (stick-breaking)
    d_C[k] = (float)C + pre;

    for (int e = 0; e < DIM; ++e) {
        float s = 0.0f;
        for (int d = 0; d < DIM; ++d)
            s = fmaf(means[k * DIM + d], P[k * DIM * DIM + d * DIM + e], s);
        d_negmuP[k * DIM + e] = -s;
    }
}

// ---------------------------------------------------------------------------
// Packed f32x2 helpers (FFMA2 SASS — 2x scalar FFMA throughput on sm_103a)
// ---------------------------------------------------------------------------
static __device__ __forceinline__ unsigned long long ff2(
    unsigned long long a, unsigned long long b, unsigned long long c) {
    unsigned long long d;
    asm("fma.rn.f32x2 %0, %1, %2, %3;" : "=l"(d) : "l"(a), "l"(b), "l"(c));
    return d;
}
static __device__ __forceinline__ unsigned long long fadd2(
    unsigned long long a, unsigned long long b) {
    unsigned long long d;
    asm("add.rn.f32x2 %0, %1, %2;" : "=l"(d) : "l"(a), "l"(b));
    return d;
}
static __device__ __forceinline__ unsigned long long pack2(float x) {
    unsigned long long d;
    asm("mov.b64 %0, {%1, %1};" : "=l"(d) : "f"(x));
    return d;
}
static __device__ __forceinline__ void unpack2(unsigned long long v, float& lo, float& hi) {
    asm("mov.b64 {%0, %1}, %2;" : "=f"(lo), "=f"(hi) : "l"(v));
}

// ---------------------------------------------------------------------------
// Main kernel: 1024 blocks x 32 threads (1 warp). One thread = one X row.
// Per k: stage P_k (16 KB) into smem; sq = ||x*P_k - mu_k*P_k||^2 with 64
// fp32 accumulators held as 32 f32x2 registers; running argmax of C_k-0.5*sq.
// OUTPUT: FLOAT32 index values (harness compares the buffer as float32).
// ---------------------------------------------------------------------------
__global__ __launch_bounds__(NTHREADS) void bgm_argmax_kernel(
    const float* __restrict__ X,
    const float* __restrict__ P,
    float* __restrict__ out) {

    __shared__ __align__(16) float Psm[DIM * DIM];                    // 16 KB
    __shared__ __align__(16) float Xsm[ROWS_PER_BLOCK * (DIM + 1)];   // padded
    __shared__ float Csm[NK];

    const int tid  = threadIdx.x;
    const int row0 = blockIdx.x * ROWS_PER_BLOCK;

    // Stage this block's X tile: float4 global loads, padded smem writes.
    {
        const float4* __restrict__ Xg =
            reinterpret_cast<const float4*>(X + row0 * DIM);
        for (int i = tid; i < ROWS_PER_BLOCK * (DIM / 4); i += NTHREADS) {
            const float4 v = Xg[i];
            const int r = i >> 4;            // 16 float4 per row
            const int c = (i & 15) << 2;
            float* dst = &Xsm[r * (DIM + 1) + c];
            dst[0] = v.x; dst[1] = v.y; dst[2] = v.z; dst[3] = v.w;
        }
    }
    for (int i = tid; i < NK; i += NTHREADS) Csm[i] = d_C[i];

    const int xbase = tid * (DIM + 1);
    float best = __int_as_float(0xff800000u);  // -inf
    int   arg  = 0;

    const unsigned long long* __restrict__ nmAll =
        reinterpret_cast<const unsigned long long*>(d_negmuP);

    for (int k = 0; k < NK; ++k) {
        __syncthreads();  // prev iter done reading Psm (covers staging at k=0)
        {
            const float4* __restrict__ Pg =
                reinterpret_cast<const float4*>(P + k * DIM * DIM);
            float4* Ps4 = reinterpret_cast<float4*>(Psm);
#pragma unroll
            for (int i = 0; i < 32; ++i)
                Ps4[tid + i * NTHREADS] = Pg[tid + i * NTHREADS];
        }
        __syncthreads();

        unsigned long long acc[32];
#pragma unroll
        for (int j = 0; j < 32; ++j) acc[j] = 0ULL;

#pragma unroll 4
        for (int d = 0; d < DIM; ++d) {
            const unsigned long long x2 = pack2(Xsm[xbase + d]);
            const ulonglong2* __restrict__ pr =
                reinterpret_cast<const ulonglong2*>(Psm + (d << 6));
#pragma unroll
            for (int j = 0; j < 16; ++j) {
                const ulonglong2 p = pr[j];       // LDS.128 broadcast: 2 f32x2 operands
                acc[2 * j]     = ff2(x2, p.x, acc[2 * j]);
                acc[2 * j + 1] = ff2(x2, p.y, acc[2 * j + 1]);
            }
        }

        // Epilogue: sq = sum_e (acc_e - muP_e)^2, two independent f32x2 chains
        const unsigned long long* __restrict__ nm = nmAll + (k << 5);
        unsigned long long sqa = 0ULL, sqb = 0ULL;
#pragma unroll
        for (int j = 0; j < 16; ++j) {
            const unsigned long long da = fadd2(acc[2 * j],     nm[2 * j]);
            const unsigned long long db = fadd2(acc[2 * j + 1], nm[2 * j + 1]);
            sqa = ff2(da, da, sqa);
            sqb = ff2(db, db, sqb);
        }
        float a0, a1, b0, b1;
        unpack2(sqa, a0, a1);
        unpack2(sqb, b0, b1);
        const float sq  = (a0 + a1) + (b0 + b1);
        const float wlp = fmaf(-0.5f, sq, Csm[k]);
        if (wlp > best) { best = wlp; arg = k; }   // strict >: first-max, like jnp.argmax
    }

    out[row0 + tid] = (float)arg;   // FLOAT output: index as value
}

// ---------------------------------------------------------------------------
// Launch. Inputs identified by ELEMENT COUNT (robust to metadata ordering):
//   X = 2097152, precisions_chol = 262144, means = 4096,
//   weight_concentration = 128, dof / mean_precision = 64 each
//   (disambiguated on-device by value). Output: float32 index values [N].
// ---------------------------------------------------------------------------
extern "C" void kernel_launch(void* const* d_in, const int* in_sizes, int n_in,
                              void* d_out, int out_size) {
    (void)out_size;
    const float* X     = nullptr;
    const float* means = nullptr;
    const float* P     = nullptr;
    const float* wc    = nullptr;
    const float* v64a  = nullptr;
    const float* v64b  = nullptr;

    for (int i = 0; i < n_in; ++i) {
        const float* p = (const float*)d_in[i];
        switch (in_sizes[i]) {
            case 2097152: X = p; break;
            case 262144:  P = p; break;
            case 4096:    means = p; break;
            case 128:     wc = p; break;
            case 64:      if (!v64a) v64a = p; else v64b = p; break;
            default: break;
        }
    }
    if (!v64b) v64b = v64a;  // defensive
    float* out = (float*)d_out;

    bgm_prep_kernel<<<1, NK>>>(means, P, wc, v64a, v64b);
    bgm_argmax_kernel<<<NBLOCKS, NTHREADS>>>(X, P, out);
}

// round 8
// speedup vs baseline: 2.0454x; 2.0454x over previous
#include <cuda_runtime.h>
#include <cstdint>

// Problem constants (N=32768, D=64, K=64 per reference)
#define NPTS 32768
#define DIM 64
#define NK 64
#define ROWS_PER_BLOCK 64
#define NTHREADS 32
#define NBLOCKS (NPTS / ROWS_PER_BLOCK)   // 512

// Scratch (allocation-free rule: __device__ globals)
__device__ __align__(16) float d_negmuP[NK * DIM];  // -(means_k @ P_k), [K,D]
__device__ float d_C[NK];                           // final per-cluster constant
__device__ float d_Cpart[NK];                       // C without stick-breaking cumsum
__device__ float d_sdb[NK];                         // digamma(b)-digamma(a+b)

// ---------------------------------------------------------------------------
// NaN-proof helpers (identity on valid inputs).
// ---------------------------------------------------------------------------
static __device__ __forceinline__ double safe_log(double v) {
    v = fabs(v);
    if (v < 1e-300) v = 1e-300;
    return log(v);
}

// digamma in double: bounded recurrence to x>=6, then asymptotic series.
static __device__ __forceinline__ double digamma_d(double x) {
    if (!(x > 1e-6)) x = 1e-6;
    double r = 0.0;
    #pragma unroll 1
    for (int it = 0; it < 8 && x < 6.0; ++it) { r -= 1.0 / x; x += 1.0; }
    double inv  = 1.0 / x;
    double inv2 = inv * inv;
    double s = inv2 * (1.0 / 12.0
             - inv2 * (1.0 / 120.0
             - inv2 * (1.0 / 252.0
             - inv2 * (1.0 / 240.0))));
    return r + log(x) - 0.5 * inv - s;
}

// ---------------------------------------------------------------------------
// Prep A: 64 blocks (one per cluster k) x 64 threads (one per dimension i).
// Thread i: digamma(0.5*(dof_k - i)), log(P[k,i,i]), negmuP column i.
// Block-reduces sum(lg + 0.5*t); thread 0 adds scalar terms.
// ---------------------------------------------------------------------------
__global__ void bgm_prep_a(const float* __restrict__ means,
                           const float* __restrict__ P,
                           const float* __restrict__ wc,
                           const float* __restrict__ v64a,
                           const float* __restrict__ v64b) {
    const int k = blockIdx.x;
    const int i = threadIdx.x;
    __shared__ double sd[NK];

    const bool a_is_dof = (v64a[0] > 32.0f);   // dof in [65,114], mp in (0.5,10]
    const float* __restrict__ dof = a_is_dof ? v64a : v64b;
    const float* __restrict__ mp  = a_is_dof ? v64b : v64a;

    const double dofk = (double)dof[k];

    const double t  = digamma_d(0.5 * (dofk - (double)i));
    const double lg = safe_log((double)P[k * DIM * DIM + i * DIM + i]);
    sd[i] = lg + 0.5 * t;
    __syncthreads();

    // negmuP column i (coalesced over i)
    {
        float s = 0.0f;
        for (int d = 0; d < DIM; ++d)
            s = fmaf(means[k * DIM + d], P[k * DIM * DIM + d * DIM + i], s);
        d_negmuP[k * DIM + i] = -s;
    }

    // tree reduce sd
    for (int off = 32; off > 0; off >>= 1) {
        if (i < off) sd[i] += sd[i + off];
        __syncthreads();
    }

    if (i == 0) {
        double mpk = (double)mp[k];
        if (!(mpk > 1e-6)) mpk = 1e-6;
        const double a  = (double)wc[k];
        const double b  = (double)wc[NK + k];
        const double ds = digamma_d(a + b);
        const double dga = digamma_d(a);
        const double dgb = digamma_d(b);
        double C = sd[0]
                 + 0.5 * (double)DIM * 0.69314718055994530942   // +0.5*D*log2
                 - 0.5 * (double)DIM * 1.8378770664093454836    // -0.5*D*log(2pi)
                 - 0.5 * (double)DIM * safe_log(dofk)
                 - 0.5 * (double)DIM / mpk
                 + dga - ds;
        d_Cpart[k] = (float)C;
        d_sdb[k]   = (float)(dgb - ds);
    }
}

// Prep B: stick-breaking exclusive cumsum (fp32, same order as reference path).
__global__ void bgm_prep_b() {
    const int k = threadIdx.x;
    float pre = 0.0f;
    for (int j = 0; j < k; ++j) pre += d_sdb[j];
    d_C[k] = d_Cpart[k] + pre;
}

// ---------------------------------------------------------------------------
// Packed f32x2 helpers (FFMA2 SASS — 2x scalar FFMA throughput on sm_103a)
// ---------------------------------------------------------------------------
static __device__ __forceinline__ unsigned long long ff2(
    unsigned long long a, unsigned long long b, unsigned long long c) {
    unsigned long long d;
    asm("fma.rn.f32x2 %0, %1, %2, %3;" : "=l"(d) : "l"(a), "l"(b), "l"(c));
    return d;
}
static __device__ __forceinline__ unsigned long long fadd2(
    unsigned long long a, unsigned long long b) {
    unsigned long long d;
    asm("add.rn.f32x2 %0, %1, %2;" : "=l"(d) : "l"(a), "l"(b));
    return d;
}
static __device__ __forceinline__ unsigned long long pack2(float x) {
    unsigned long long d;
    asm("mov.b64 %0, {%1, %1};" : "=l"(d) : "f"(x));
    return d;
}
static __device__ __forceinline__ void unpack2(unsigned long long v, float& lo, float& hi) {
    asm("mov.b64 {%0, %1}, %2;" : "=f"(lo), "=f"(hi) : "l"(v));
}

// cp.async 16B helpers
static __device__ __forceinline__ void cp16(uint32_t smem_addr, const void* gptr) {
    asm volatile("cp.async.cg.shared.global [%0], [%1], 16;" :: "r"(smem_addr), "l"(gptr));
}
static __device__ __forceinline__ void cp_commit() {
    asm volatile("cp.async.commit_group;");
}
template <int N>
static __device__ __forceinline__ void cp_wait() {
    asm volatile("cp.async.wait_group %0;" :: "n"(N));
}

// ---------------------------------------------------------------------------
// Main kernel: 512 blocks x 32 threads (1 warp). Thread t owns rows t, t+32.
// Per k (double-buffered P via cp.async): two e-half passes over d, 2 rows x
// 16 f32x2 accumulators each; running argmax of C_k - 0.5*sq per row.
// OUTPUT: float32 index values.
// ---------------------------------------------------------------------------
__global__ __launch_bounds__(NTHREADS) void bgm_argmax_kernel(
    const float* __restrict__ X,
    const float* __restrict__ P,
    float* __restrict__ out) {

    __shared__ __align__(16) float Psm[2][DIM * DIM];                 // 2 x 16 KB
    __shared__ __align__(16) float Xsm[ROWS_PER_BLOCK * (DIM + 1)];   // padded
    __shared__ float Csm[NK];

    const int tid  = threadIdx.x;
    const int row0 = blockIdx.x * ROWS_PER_BLOCK;

    // Stage X tile: 64 rows -> 1024 float4, 32 per thread.
    {
        const float4* __restrict__ Xg =
            reinterpret_cast<const float4*>(X + row0 * DIM);
        for (int i = tid; i < ROWS_PER_BLOCK * (DIM / 4); i += NTHREADS) {
            const float4 v = Xg[i];
            const int r = i >> 4;
            const int c = (i & 15) << 2;
            float* dst = &Xsm[r * (DIM + 1) + c];
            dst[0] = v.x; dst[1] = v.y; dst[2] = v.z; dst[3] = v.w;
        }
    }
    for (int i = tid; i < NK; i += NTHREADS) Csm[i] = d_C[i];

    // Prologue: stage P_0 into buffer 0
    {
        const float4* src = reinterpret_cast<const float4*>(P);
        const uint32_t dst = (uint32_t)__cvta_generic_to_shared(&Psm[0][0]);
#pragma unroll
        for (int j = 0; j < 32; ++j)
            cp16(dst + (tid + j * 32) * 16, src + tid + j * 32);
        cp_commit();
    }

    const int xb0 = tid * (DIM + 1);
    const int xb1 = (tid + 32) * (DIM + 1);
    float best0 = __int_as_float(0xff800000u), best1 = best0;
    int   arg0 = 0, arg1 = 0;

    const unsigned long long* __restrict__ nmAll =
        reinterpret_cast<const unsigned long long*>(d_negmuP);

    for (int k = 0; k < NK; ++k) {
        // Prefetch P_{k+1} into the other buffer
        if (k + 1 < NK) {
            const float4* src = reinterpret_cast<const float4*>(P + (k + 1) * DIM * DIM);
            const uint32_t dst =
                (uint32_t)__cvta_generic_to_shared(&Psm[(k + 1) & 1][0]);
#pragma unroll
            for (int j = 0; j < 32; ++j)
                cp16(dst + (tid + j * 32) * 16, src + tid + j * 32);
            cp_commit();
            cp_wait<1>();   // P_k ready; P_{k+1} in flight
        } else {
            cp_wait<0>();
        }
        __syncwarp();

        const float* __restrict__ Pk = Psm[k & 1];
        float sq0 = 0.0f, sq1 = 0.0f;

#pragma unroll
        for (int h = 0; h < 2; ++h) {
            unsigned long long a0[16], a1[16];
#pragma unroll
            for (int j = 0; j < 16; ++j) { a0[j] = 0ULL; a1[j] = 0ULL; }

#pragma unroll 4
            for (int d = 0; d < DIM; ++d) {
                const unsigned long long x0 = pack2(Xsm[xb0 + d]);
                const unsigned long long x1 = pack2(Xsm[xb1 + d]);
                const ulonglong2* __restrict__ pr =
                    reinterpret_cast<const ulonglong2*>(Pk + (d << 6) + (h << 5));
#pragma unroll
                for (int j = 0; j < 8; ++j) {
                    const ulonglong2 p = pr[j];   // LDS.128 broadcast
                    a0[2 * j]     = ff2(x0, p.x, a0[2 * j]);
                    a0[2 * j + 1] = ff2(x0, p.y, a0[2 * j + 1]);
                    a1[2 * j]     = ff2(x1, p.x, a1[2 * j]);
                    a1[2 * j + 1] = ff2(x1, p.y, a1[2 * j + 1]);
                }
            }

            // Half-epilogue: sq += sum_e (acc_e + negmuP_e)^2
            const unsigned long long* __restrict__ nm = nmAll + (k << 5) + (h << 4);
            unsigned long long s0 = 0ULL, s1 = 0ULL;
#pragma unroll
            for (int j = 0; j < 16; ++j) {
                const unsigned long long m = nm[j];
                const unsigned long long e0 = fadd2(a0[j], m);
                const unsigned long long e1 = fadd2(a1[j], m);
                s0 = ff2(e0, e0, s0);
                s1 = ff2(e1, e1, s1);
            }
            float l0, h0, l1, h1;
            unpack2(s0, l0, h0);
            unpack2(s1, l1, h1);
            sq0 += l0 + h0;
            sq1 += l1 + h1;
        }

        const float Ck = Csm[k];
        const float w0 = fmaf(-0.5f, sq0, Ck);
        const float w1 = fmaf(-0.5f, sq1, Ck);
        if (w0 > best0) { best0 = w0; arg0 = k; }
        if (w1 > best1) { best1 = w1; arg1 = k; }
    }

    out[row0 + tid]      = (float)arg0;
    out[row0 + tid + 32] = (float)arg1;
}

// ---------------------------------------------------------------------------
// Launch. Inputs identified by ELEMENT COUNT; dof/mp disambiguated on device.
// Output: float32 index values [N].
// ---------------------------------------------------------------------------
extern "C" void kernel_launch(void* const* d_in, const int* in_sizes, int n_in,
                              void* d_out, int out_size) {
    (void)out_size;
    const float* X     = nullptr;
    const float* means = nullptr;
    const float* P     = nullptr;
    const float* wc    = nullptr;
    const float* v64a  = nullptr;
    const float* v64b  = nullptr;

    for (int i = 0; i < n_in; ++i) {
        const float* p = (const float*)d_in[i];
        switch (in_sizes[i]) {
            case 2097152: X = p; break;
            case 262144:  P = p; break;
            case 4096:    means = p; break;
            case 128:     wc = p; break;
            case 64:      if (!v64a) v64a = p; else v64b = p; break;
            default: break;
        }
    }
    if (!v64b) v64b = v64a;  // defensive
    float* out = (float*)d_out;

    bgm_prep_a<<<NK, DIM>>>(means, P, wc, v64a, v64b);
    bgm_prep_b<<<1, NK>>>();
    bgm_argmax_kernel<<<NBLOCKS, NTHREADS>>>(X, P, out);
}

// round 9
// speedup vs baseline: 2.5224x; 1.2332x over previous
#include <cuda_runtime.h>
#include <cstdint>

// Problem constants (N=32768, D=64, K=64 per reference)
#define NPTS 32768
#define DIM 64
#define NK 64
#define ROWS_PER_BLOCK 64
#define NTHREADS 32
#define NBLOCKS (NPTS / ROWS_PER_BLOCK)   // 512

// Scratch (allocation-free rule: __device__ globals)
__device__ __align__(16) float d_negmuP[NK * DIM];  // -(means_k @ P_k), [K,D]
__device__ float d_C[NK];                           // final per-cluster constant
__device__ float d_Cpart[NK];                       // C without stick-breaking cumsum
__device__ float d_sdb[NK];                         // digamma(b)-digamma(a+b)

// ---------------------------------------------------------------------------
// NaN-proof helpers (identity on valid inputs).
// ---------------------------------------------------------------------------
static __device__ __forceinline__ double safe_log(double v) {
    v = fabs(v);
    if (v < 1e-300) v = 1e-300;
    return log(v);
}

// digamma in double: bounded recurrence to x>=6, then asymptotic series.
static __device__ __forceinline__ double digamma_d(double x) {
    if (!(x > 1e-6)) x = 1e-6;
    double r = 0.0;
    #pragma unroll 1
    for (int it = 0; it < 8 && x < 6.0; ++it) { r -= 1.0 / x; x += 1.0; }
    double inv  = 1.0 / x;
    double inv2 = inv * inv;
    double s = inv2 * (1.0 / 12.0
             - inv2 * (1.0 / 120.0
             - inv2 * (1.0 / 252.0
             - inv2 * (1.0 / 240.0))));
    return r + log(x) - 0.5 * inv - s;
}

// ---------------------------------------------------------------------------
// Prep A: 64 blocks (cluster k) x 64 threads (dimension i).
// ---------------------------------------------------------------------------
__global__ void bgm_prep_a(const float* __restrict__ means,
                           const float* __restrict__ P,
                           const float* __restrict__ wc,
                           const float* __restrict__ v64a,
                           const float* __restrict__ v64b) {
    const int k = blockIdx.x;
    const int i = threadIdx.x;
    __shared__ double sd[NK];

    const bool a_is_dof = (v64a[0] > 32.0f);   // dof in [65,114], mp in (0.5,10]
    const float* __restrict__ dof = a_is_dof ? v64a : v64b;
    const float* __restrict__ mp  = a_is_dof ? v64b : v64a;

    const double dofk = (double)dof[k];

    const double t  = digamma_d(0.5 * (dofk - (double)i));
    const double lg = safe_log((double)P[k * DIM * DIM + i * DIM + i]);
    sd[i] = lg + 0.5 * t;
    __syncthreads();

    // negmuP column i (coalesced over i)
    {
        float s = 0.0f;
        for (int d = 0; d < DIM; ++d)
            s = fmaf(means[k * DIM + d], P[k * DIM * DIM + d * DIM + i], s);
        d_negmuP[k * DIM + i] = -s;
    }

    for (int off = 32; off > 0; off >>= 1) {
        if (i < off) sd[i] += sd[i + off];
        __syncthreads();
    }

    if (i == 0) {
        double mpk = (double)mp[k];
        if (!(mpk > 1e-6)) mpk = 1e-6;
        const double a  = (double)wc[k];
        const double b  = (double)wc[NK + k];
        const double ds = digamma_d(a + b);
        const double dga = digamma_d(a);
        const double dgb = digamma_d(b);
        double C = sd[0]
                 + 0.5 * (double)DIM * 0.69314718055994530942   // +0.5*D*log2
                 - 0.5 * (double)DIM * 1.8378770664093454836    // -0.5*D*log(2pi)
                 - 0.5 * (double)DIM * safe_log(dofk)
                 - 0.5 * (double)DIM / mpk
                 + dga - ds;
        d_Cpart[k] = (float)C;
        d_sdb[k]   = (float)(dgb - ds);
    }
}

// Prep B: stick-breaking exclusive cumsum.
__global__ void bgm_prep_b() {
    const int k = threadIdx.x;
    float pre = 0.0f;
    for (int j = 0; j < k; ++j) pre += d_sdb[j];
    d_C[k] = d_Cpart[k] + pre;
}

// ---------------------------------------------------------------------------
// Packed f32x2 helpers (FFMA2 SASS — 2x scalar FFMA throughput on sm_103a)
// ---------------------------------------------------------------------------
static __device__ __forceinline__ unsigned long long ff2(
    unsigned long long a, unsigned long long b, unsigned long long c) {
    unsigned long long d;
    asm("fma.rn.f32x2 %0, %1, %2, %3;" : "=l"(d) : "l"(a), "l"(b), "l"(c));
    return d;
}
static __device__ __forceinline__ unsigned long long fadd2(
    unsigned long long a, unsigned long long b) {
    unsigned long long d;
    asm("add.rn.f32x2 %0, %1, %2;" : "=l"(d) : "l"(a), "l"(b));
    return d;
}
static __device__ __forceinline__ unsigned long long pack2(float x) {
    unsigned long long d;
    asm("mov.b64 %0, {%1, %1};" : "=l"(d) : "f"(x));
    return d;
}
static __device__ __forceinline__ void unpack2(unsigned long long v, float& lo, float& hi) {
    asm("mov.b64 {%0, %1}, %2;" : "=f"(lo), "=f"(hi) : "l"(v));
}

// cp.async 16B helpers
static __device__ __forceinline__ void cp16(uint32_t smem_addr, const void* gptr) {
    asm volatile("cp.async.cg.shared.global [%0], [%1], 16;" :: "r"(smem_addr), "l"(gptr));
}
static __device__ __forceinline__ void cp_commit() {
    asm volatile("cp.async.commit_group;");
}
template <int N>
static __device__ __forceinline__ void cp_wait() {
    asm volatile("cp.async.wait_group %0;" :: "n"(N));
}

// ---------------------------------------------------------------------------
// Main kernel: 512 blocks x 32 threads. Thread t owns rows t, t+32.
// P_k is UPPER-TRIANGULAR: P[d][e]=0 for d>e. y_e = sum_{d<=e} x_d P[d][e].
// Process e in 4 quarters; quarter q only needs d < 16(q+1) (bit-exact skip
// of the zero terms -> 37.5% fewer MACs, smaller live accumulator set).
// Per-pass acc: 2 rows x 8 f32x2. cp.async double-buffered P staging.
// OUTPUT: float32 index values.
// ---------------------------------------------------------------------------
__global__ __launch_bounds__(NTHREADS) void bgm_argmax_kernel(
    const float* __restrict__ X,
    const float* __restrict__ P,
    float* __restrict__ out) {

    __shared__ __align__(16) float Psm[2][DIM * DIM];                 // 2 x 16 KB
    __shared__ __align__(16) float Xsm[ROWS_PER_BLOCK * (DIM + 1)];   // padded
    __shared__ float Csm[NK];

    const int tid  = threadIdx.x;
    const int row0 = blockIdx.x * ROWS_PER_BLOCK;

    // Stage X tile: 64 rows -> 1024 float4, 32 per thread.
    {
        const float4* __restrict__ Xg =
            reinterpret_cast<const float4*>(X + row0 * DIM);
        for (int i = tid; i < ROWS_PER_BLOCK * (DIM / 4); i += NTHREADS) {
            const float4 v = Xg[i];
            const int r = i >> 4;
            const int c = (i & 15) << 2;
            float* dst = &Xsm[r * (DIM + 1) + c];
            dst[0] = v.x; dst[1] = v.y; dst[2] = v.z; dst[3] = v.w;
        }
    }
    for (int i = tid; i < NK; i += NTHREADS) Csm[i] = d_C[i];

    // Prologue: stage P_0 into buffer 0
    {
        const float4* src = reinterpret_cast<const float4*>(P);
        const uint32_t dst = (uint32_t)__cvta_generic_to_shared(&Psm[0][0]);
#pragma unroll
        for (int j = 0; j < 32; ++j)
            cp16(dst + (tid + j * 32) * 16, src + tid + j * 32);
        cp_commit();
    }

    const int xb0 = tid * (DIM + 1);
    const int xb1 = (tid + 32) * (DIM + 1);
    float best0 = __int_as_float(0xff800000u), best1 = best0;
    int   arg0 = 0, arg1 = 0;

    const ulonglong2* __restrict__ nmAll =
        reinterpret_cast<const ulonglong2*>(d_negmuP);

    for (int k = 0; k < NK; ++k) {
        // Prefetch P_{k+1} into the other buffer
        if (k + 1 < NK) {
            const float4* src = reinterpret_cast<const float4*>(P + (k + 1) * DIM * DIM);
            const uint32_t dst =
                (uint32_t)__cvta_generic_to_shared(&Psm[(k + 1) & 1][0]);
#pragma unroll
            for (int j = 0; j < 32; ++j)
                cp16(dst + (tid + j * 32) * 16, src + tid + j * 32);
            cp_commit();
            cp_wait<1>();   // P_k ready; P_{k+1} in flight
        } else {
            cp_wait<0>();
        }
        __syncwarp();

        const float* __restrict__ Pk = Psm[k & 1];
        unsigned long long s0 = 0ULL, s1 = 0ULL;   // running sq as f32x2 pairs

#pragma unroll
        for (int q = 0; q < 4; ++q) {              // e-quarter [16q, 16q+16)
            unsigned long long a0[8], a1[8];
#pragma unroll
            for (int j = 0; j < 8; ++j) { a0[j] = 0ULL; a1[j] = 0ULL; }

            const int dmax = 16 * (q + 1);         // triangular bound (compile-time)
#pragma unroll 4
            for (int d = 0; d < dmax; ++d) {
                const unsigned long long x0 = pack2(Xsm[xb0 + d]);
                const unsigned long long x1 = pack2(Xsm[xb1 + d]);
                const ulonglong2* __restrict__ pr =
                    reinterpret_cast<const ulonglong2*>(Pk + (d << 6) + (q << 4));
#pragma unroll
                for (int j = 0; j < 4; ++j) {
                    const ulonglong2 p = pr[j];    // LDS.128 broadcast: 2 f32x2
                    a0[2 * j]     = ff2(x0, p.x, a0[2 * j]);
                    a0[2 * j + 1] = ff2(x0, p.y, a0[2 * j + 1]);
                    a1[2 * j]     = ff2(x1, p.x, a1[2 * j]);
                    a1[2 * j + 1] = ff2(x1, p.y, a1[2 * j + 1]);
                }
            }

            // Quarter epilogue: s += (acc + negmuP_quarter)^2
            const ulonglong2* __restrict__ nm = nmAll + (k << 4) + (q << 2);
#pragma unroll
            for (int j = 0; j < 4; ++j) {
                const ulonglong2 m = nm[j];
                const unsigned long long e0a = fadd2(a0[2 * j],     m.x);
                const unsigned long long e0b = fadd2(a0[2 * j + 1], m.y);
                const unsigned long long e1a = fadd2(a1[2 * j],     m.x);
                const unsigned long long e1b = fadd2(a1[2 * j + 1], m.y);
                s0 = ff2(e0a, e0a, s0);
                s0 = ff2(e0b, e0b, s0);
                s1 = ff2(e1a, e1a, s1);
                s1 = ff2(e1b, e1b, s1);
            }
        }

        float l0, h0, l1, h1;
        unpack2(s0, l0, h0);
        unpack2(s1, l1, h1);
        const float sq0 = l0 + h0;
        const float sq1 = l1 + h1;

        const float Ck = Csm[k];
        const float w0 = fmaf(-0.5f, sq0, Ck);
        const float w1 = fmaf(-0.5f, sq1, Ck);
        if (w0 > best0) { best0 = w0; arg0 = k; }
        if (w1 > best1) { best1 = w1; arg1 = k; }
    }

    out[row0 + tid]      = (float)arg0;
    out[row0 + tid + 32] = (float)arg1;
}

// ---------------------------------------------------------------------------
// Launch. Inputs identified by ELEMENT COUNT; dof/mp disambiguated on device.
// Output: float32 index values [N].
// ---------------------------------------------------------------------------
extern "C" void kernel_launch(void* const* d_in, const int* in_sizes, int n_in,
                              void* d_out, int out_size) {
    (void)out_size;
    const float* X     = nullptr;
    const float* means = nullptr;
    const float* P     = nullptr;
    const float* wc    = nullptr;
    const float* v64a  = nullptr;
    const float* v64b  = nullptr;

    for (int i = 0; i < n_in; ++i) {
        const float* p = (const float*)d_in[i];
        switch (in_sizes[i]) {
            case 2097152: X = p; break;
            case 262144:  P = p; break;
            case 4096:    means = p; break;
            case 128:     wc = p; break;
            case 64:      if (!v64a) v64a = p; else v64b = p; break;
            default: break;
        }
    }
    if (!v64b) v64b = v64a;  // defensive
    float* out = (float*)d_out;

    bgm_prep_a<<<NK, DIM>>>(means, P, wc, v64a, v64b);
    bgm_prep_b<<<1, NK>>>();
    bgm_argmax_kernel<<<NBLOCKS, NTHREADS>>>(X, P, out);
}